// round 13
// baseline (speedup 1.0000x reference)
#include <cuda_runtime.h>
#include <cuda_bf16.h>

// Output: 8192 x 8192 fp32, zeros except diag(triggers * mask).
//
// FINAL (v2 of best config): pure-write fill at the HBM write-drain ceiling
// (~6.9 TB/s effective; confirmed across memset/STG.128/STG.256/wt/TMA-bulk).
// One-shot grid, 256-bit zero stores, 4096 floats (half a row) per warp =
// 16 front-batched STG.256 per warp for maximum store MLP; the diagonal is
// overwritten afterwards by the same thread that zeroed it (program-order
// correct). 2048 blocks x 256 threads.

static constexpr int N = 8192;                 // row = 8192 floats = 32 KB
static constexpr int FLOATS_PER_WARP = 4096;   // half-row per warp
static constexpr int ITERS = 16;               // 16 x (32 lanes x 32B) = 4096 floats

__device__ __forceinline__ void stg256_zero(float* p) {
    asm volatile("st.global.v8.f32 [%0], {%1,%1,%1,%1,%1,%1,%1,%1};"
                 :: "l"(p), "f"(0.0f) : "memory");
}

__global__ void __launch_bounds__(256)
fill_diag_kernel(const float* __restrict__ triggers,
                 const int* __restrict__ mask,
                 float* __restrict__ out) {
    const unsigned tid  = blockIdx.x * blockDim.x + threadIdx.x;
    const unsigned warp = tid >> 5;
    const unsigned lane = tid & 31;

    // This warp's region: floats [startf, startf + 4096) — within one row
    // (4096 | 8192).
    const size_t startf = (size_t)warp * FLOATS_PER_WARP;
    float* base = out + startf + (size_t)lane * 8;

    // ---- Bulk zero-fill: 16 front-batched 1KB-contiguous STG.256 ----
#pragma unroll
    for (int i = 0; i < ITERS; i++)
        stg256_zero(base + (size_t)i * 256);

    // ---- Diagonal fix-up ----
    // Row r's diagonal element (col r) is in this warp's range iff
    // d = r - c0 in [0, 4096). Owning lane under the v8 layout is
    // ((d>>3) & 31) — the same thread that zeroed that address above,
    // so program order guarantees the final value.
    const unsigned r  = (unsigned)(startf >> 13);   // row (N = 2^13)
    const unsigned c0 = (unsigned)(startf & (N - 1));
    const unsigned d  = r - c0;                     // wraps large if r < c0
    if (d < (unsigned)FLOATS_PER_WARP && ((d >> 3) & 31) == lane) {
        out[startf + d] = triggers[r] * (float)mask[r];
    }
}

extern "C" void kernel_launch(void* const* d_in, const int* in_sizes, int n_in,
                              void* d_out, int out_size) {
    const float* triggers = (const float*)d_in[0];
    const int*   mask     = (const int*)d_in[1];
    float*       out      = (float*)d_out;

    // 67,108,864 floats; 4096 per warp => 16384 warps => 2048 blocks of 256.
    const int blocks = (int)(((size_t)N * N / FLOATS_PER_WARP * 32) / 256);
    fill_diag_kernel<<<blocks, 256>>>(triggers, mask, out);
}

// round 14
// speedup vs baseline: 1.0486x; 1.0486x over previous
#include <cuda_runtime.h>
#include <cuda_bf16.h>

// Output: 8192 x 8192 fp32, zeros except diag(triggers * mask).
//
// FINAL — exact best-measured configuration (R3: 41.09us total).
// Pure-write fill at the HBM write-drain ceiling (~6.9-7.0 TB/s effective,
// confirmed by driver memset, STG.128, STG.256, st.wt, and TMA bulk all
// converging). Byte-reduction schemes (evict hints, read-elision,
// hot/stream split) are structurally neutral-or-worse: dirty L2 lines
// drain eagerly between graph replays, reads cost the same as writes at
// the LTS cap, no L2 policy window is available, and determinism rules
// ban cross-call state. Work-per-warp measured both directions; 2048
// floats/warp (8x STG.256) at 4096x256 is the optimum.
//
// Layout: each warp owns one quarter-row (2048 floats, contiguous 8KB);
// each STG.256 is a perfectly-coalesced 1KB warp wavefront. The diagonal
// element is overwritten AFTER the zero stores by the same thread that
// zeroed its address, so plain program order guarantees the final value
// (no sync, no second kernel). Only 32 of 32768 warps touch the diagonal.

static constexpr int N = 8192;                 // row = 8192 floats = 32 KB
static constexpr int FLOATS_PER_WARP = 2048;   // quarter-row per warp
static constexpr int ITERS = 8;                // 8 x (32 lanes x 32B) = 2048 floats

__device__ __forceinline__ void stg256_zero(float* p) {
    asm volatile("st.global.v8.f32 [%0], {%1,%1,%1,%1,%1,%1,%1,%1};"
                 :: "l"(p), "f"(0.0f) : "memory");
}

__global__ void __launch_bounds__(256)
fill_diag_kernel(const float* __restrict__ triggers,
                 const int* __restrict__ mask,
                 float* __restrict__ out) {
    const unsigned tid  = blockIdx.x * blockDim.x + threadIdx.x;
    const unsigned warp = tid >> 5;
    const unsigned lane = tid & 31;

    // This warp's region: floats [startf, startf + 2048)
    const size_t startf = (size_t)warp * FLOATS_PER_WARP;
    float* base = out + startf + (size_t)lane * 8;

    // ---- Bulk zero-fill: each STG.256 is a contiguous 1KB warp wavefront ----
#pragma unroll
    for (int i = 0; i < ITERS; i++) {
        stg256_zero(base + (size_t)i * 256);
    }

    // ---- Diagonal fix-up ----
    // The warp's 2048 floats lie within one row (2048 | 8192). Row r's
    // diagonal element (column r) is in this warp's range iff d = r - c0
    // is in [0, 2048). The owning lane for float offset d under the v8
    // layout is ((d>>3) & 31) — exactly the thread that zeroed that
    // address above, so program order gives the final value.
    const unsigned r  = (unsigned)(startf >> 13);   // row (N = 2^13)
    const unsigned c0 = (unsigned)(startf & (N - 1));
    const unsigned d  = r - c0;                     // unsigned wrap => large if r < c0
    if (d < (unsigned)FLOATS_PER_WARP && ((d >> 3) & 31) == lane) {
        out[startf + d] = triggers[r] * (float)mask[r];
    }
}

extern "C" void kernel_launch(void* const* d_in, const int* in_sizes, int n_in,
                              void* d_out, int out_size) {
    const float* triggers = (const float*)d_in[0];
    const int*   mask     = (const int*)d_in[1];
    float*       out      = (float*)d_out;

    // Total floats = N*N = 67,108,864; 2048 per warp => 32768 warps
    // => 4096 blocks of 256 threads.
    const int blocks = (int)(((size_t)N * N / FLOATS_PER_WARP * 32) / 256);
    fill_diag_kernel<<<blocks, 256>>>(triggers, mask, out);
}